// round 16
// baseline (speedup 1.0000x reference)
#include <cuda_runtime.h>
#include <cstdint>
#include <math.h>

// Problem dims (fixed by setup_inputs)
#define TNUM 4096
#define DDIM 1024
#define HDIM 4096
#define ODIM 1024
#define ENUM 8
#define NROWS (TNUM * 2)

// ---------------- scratch (static __device__, no allocs) ----------------
// ONLY referenced from device code (host-side use passes shadow symbol!)
__device__ int   g_counts[ENUM];
__device__ int   g_offsets[ENUM];
__device__ int   g_e[NROWS];
__device__ int   g_pos[NROWS];
__device__ float g_gate[NROWS];
__device__ int   g_row_token[NROWS];
__device__ int   g_token_rows[NROWS];
__device__ float g_xr[(size_t)TNUM * DDIM];            // x rounded to tf32 (16 MB)
__device__ float g_w1t[(size_t)ENUM * HDIM * DDIM];    // W1^T rounded [E][H][D] (128 MB)
__device__ float g_w2t[(size_t)ENUM * ODIM * HDIM];    // W2^T rounded [E][O][H] (128 MB)
__device__ float g_h[(size_t)NROWS * HDIM];            // tf32-rounded intermediate (128 MB)
__device__ float g_y[(size_t)NROWS * ODIM];            // expert outputs (32 MB)

__device__ __forceinline__ float rna_tf32(float f) {
    uint32_t u;
    asm("cvt.rna.tf32.f32 %0, %1;" : "=r"(u) : "f"(f));
    return __uint_as_float(u);
}
__device__ __forceinline__ uint32_t smem_u32(const void* p) {
    uint32_t a;
    asm("{ .reg .u64 t; cvta.to.shared.u64 t, %1; cvt.u32.u64 %0, t; }" : "=r"(a) : "l"(p));
    return a;
}

// ---------------- prep: round x + transpose/round W1, W2 (one launch) -------
#define NB_RX (TNUM * DDIM / 4 / 256)                       // 4096
#define NT1   ((HDIM / 32) * (DDIM / 32) * ENUM)            // 32768
#define NT2   ((ODIM / 32) * (HDIM / 32) * ENUM)            // 32768

__device__ __forceinline__ void transpose_round_tile(
    const float* __restrict__ W, float* __restrict__ Wt,
    int R, int C, int bb, int tid, float (*tile)[33]) {
    int nC = C / 32;
    int per = nC * (R / 32);
    int e = bb / per;
    int rem = bb % per;
    int c0 = (rem % nC) * 32;
    int r0 = (rem / nC) * 32;
    const float* Wp = W + (size_t)e * R * C;
    float* Op = Wt + (size_t)e * R * C;
    int tx = tid & 31, ty = tid >> 5;
#pragma unroll
    for (int i = 0; i < 4; i++)
        tile[ty + i * 8][tx] = Wp[(size_t)(r0 + ty + i * 8) * C + c0 + tx];
    __syncthreads();
#pragma unroll
    for (int i = 0; i < 4; i++)
        Op[(size_t)(c0 + ty + i * 8) * R + r0 + tx] = rna_tf32(tile[tx][ty + i * 8]);
}

__global__ void prep_kernel(const float* __restrict__ x,
                            const float* __restrict__ W1,
                            const float* __restrict__ W2) {
    __shared__ float tile[32][33];
    int b = blockIdx.x, tid = threadIdx.x;
    if (b < NB_RX) {
        if (b == 0 && tid < ENUM) g_counts[tid] = 0;
        int i = b * 256 + tid;
        float4 v = *(const float4*)(x + (size_t)i * 4);
        v.x = rna_tf32(v.x); v.y = rna_tf32(v.y);
        v.z = rna_tf32(v.z); v.w = rna_tf32(v.w);
        *(float4*)(g_xr + (size_t)i * 4) = v;
    } else if (b < NB_RX + NT1) {
        transpose_round_tile(W1, g_w1t, DDIM, HDIM, b - NB_RX, tid, tile);
    } else {
        transpose_round_tile(W2, g_w2t, HDIM, ODIM, b - NB_RX - NT1, tid, tile);
    }
}

// ---------------- router ----------------
__global__ void router_kernel(const float* __restrict__ x,
                              const float* __restrict__ Wr,
                              const float* __restrict__ br) {
    int warp = threadIdx.x >> 5;
    int lane = threadIdx.x & 31;
    int t = blockIdx.x * 8 + warp;
    if (t >= TNUM) return;
    const float* xr = x + (size_t)t * DDIM;
    float acc[ENUM];
#pragma unroll
    for (int e = 0; e < ENUM; e++) acc[e] = 0.f;
    for (int d = lane; d < DDIM; d += 32) {
        float xv = xr[d];
        const float* w = Wr + (size_t)d * ENUM;
#pragma unroll
        for (int e = 0; e < ENUM; e++) acc[e] = fmaf(xv, w[e], acc[e]);
    }
#pragma unroll
    for (int e = 0; e < ENUM; e++) {
#pragma unroll
        for (int s = 16; s > 0; s >>= 1)
            acc[e] += __shfl_xor_sync(0xffffffffu, acc[e], s);
    }
    if (lane == 0) {
        float v[ENUM];
#pragma unroll
        for (int e = 0; e < ENUM; e++) v[e] = acc[e] + br[e];
        int i0 = 0; float v0 = v[0];
#pragma unroll
        for (int e = 1; e < ENUM; e++) if (v[e] > v0) { v0 = v[e]; i0 = e; }
        int i1 = -1; float v1 = -1e30f;
#pragma unroll
        for (int e = 0; e < ENUM; e++)
            if (e != i0 && v[e] > v1) { v1 = v[e]; i1 = e; }
        float g0 = 1.f / (1.f + expf(v1 - v0));
        float g1 = 1.f - g0;
        int p0 = atomicAdd(&g_counts[i0], 1);
        int p1 = atomicAdd(&g_counts[i1], 1);
        g_e[2 * t]     = i0; g_pos[2 * t]     = p0; g_gate[2 * t]     = g0;
        g_e[2 * t + 1] = i1; g_pos[2 * t + 1] = p1; g_gate[2 * t + 1] = g1;
    }
}

// build_rows with per-block local offsets
__global__ void build_rows_kernel() {
    int off[ENUM];
    {
        int s = 0;
#pragma unroll
        for (int e = 0; e < ENUM; e++) { off[e] = s; s += g_counts[e]; }
    }
    if (blockIdx.x == 0 && threadIdx.x < ENUM) g_offsets[threadIdx.x] = off[threadIdx.x];
    int t = blockIdx.x * blockDim.x + threadIdx.x;
    if (t >= TNUM) return;
#pragma unroll
    for (int k = 0; k < 2; k++) {
        int e = g_e[2 * t + k];
        int row = off[e] + g_pos[2 * t + k];
        g_row_token[row] = t;
        g_token_rows[2 * t + k] = row;
    }
}

// -- grouped GEMM: 128x256 tile, 512 thr, 4x4 warp grid, LDSM A+B, 3-stage ---
#define BM 128
#define BN 256
#define BK 32
#define S_STRIDE 36                                    // 144B rows, LDSM-safe
#define A_STAGE_BYTES (BM * S_STRIDE * 4)              // 18432
#define B_STAGE_BYTES (BN * S_STRIDE * 4)              // 36864
#define STAGE_BYTES (A_STAGE_BYTES + B_STAGE_BYTES)    // 55296
#define NSTAGE 3
#define DYN_SMEM (NSTAGE * STAGE_BYTES)                // 165888

#define CP_ASYNC16(dst, src) \
    asm volatile("cp.async.cg.shared.global [%0], [%1], 16;" \
                 :: "r"(dst), "l"(src) : "memory")
#define CP_COMMIT() asm volatile("cp.async.commit_group;" ::: "memory")
#define CP_WAIT1()  asm volatile("cp.async.wait_group 1;" ::: "memory")

#define LDSM_X4(r0, r1, r2, r3, addr) \
    asm volatile("ldmatrix.sync.aligned.m8n8.x4.shared.b16 {%0,%1,%2,%3}, [%4];" \
                 : "=r"(r0), "=r"(r1), "=r"(r2), "=r"(r3) : "r"(addr))

// PHASE 1: A = g_xr gathered via row->token (K=DDIM), B = g_w1t, C = g_h
// PHASE 2: A = g_h direct rows (K=HDIM),             B = g_w2t, C = g_y
template <int PHASE, int KD, int ND>
__global__ void __launch_bounds__(512, 1) moe_gemm_kernel(
    const float* __restrict__ biasB) {  // [E, ND] (harness ptr)
    int e = blockIdx.z;
    int cnt = g_counts[e];
    int m0 = blockIdx.y * BM;
    if (m0 >= cnt) return;
    int rbase = g_offsets[e] + m0;
    int n0 = blockIdx.x * BN;

    const float* Aglob = (PHASE == 1) ? g_xr  : g_h;    // device-side select
    const float* Btr   = (PHASE == 1) ? g_w1t : g_w2t;  // K-major rounded

    extern __shared__ __align__(16) char dynsmem[];
    __shared__ uint32_t sAoff[BM];

    int tid  = threadIdx.x;
    int lane = tid & 31;
    int warp = tid >> 5;            // 0..15

    if (tid < BM) {
        uint32_t off = 0;
        if (m0 + tid < cnt) {
            int row = rbase + tid;
            off = (PHASE == 1) ? (uint32_t)g_row_token[row] * (uint32_t)KD
                               : (uint32_t)row * (uint32_t)KD;
        }
        sAoff[tid] = off;
    }
    __syncthreads();

    // cp.async mapping: 2 A granules + 4 B granules per thread (16B each)
    uint32_t base0 = smem_u32(dynsmem);
    const char* aSrc[2];
    uint32_t    aDst[2];
    const char* bSrc[4];
    uint32_t    bDst[4];
#pragma unroll
    for (int i = 0; i < 2; i++) {
        int idx = tid + 512 * i;        // 0..1023
        int row = idx >> 3;             // 0..127
        int gg  = idx & 7;
        aSrc[i] = (const char*)Aglob + (size_t)sAoff[row] * 4 + gg * 16;
        aDst[i] = (uint32_t)(row * (S_STRIDE * 4) + gg * 16);
    }
#pragma unroll
    for (int i = 0; i < 4; i++) {
        int idx = tid + 512 * i;        // 0..2047
        int row = idx >> 3;             // 0..255
        int gg  = idx & 7;
        bSrc[i] = (const char*)Btr + ((size_t)(e * ND + n0 + row) * KD) * 4 + gg * 16;
        bDst[i] = (uint32_t)(A_STAGE_BYTES + row * (S_STRIDE * 4) + gg * 16);
    }

    const int NK = KD / BK;

    // prologue: stages 0 and 1
#pragma unroll
    for (int s = 0; s < 2; s++) {
        uint32_t sb = base0 + s * STAGE_BYTES;
        size_t adv = (size_t)s * (BK * 4);
#pragma unroll
        for (int i = 0; i < 2; i++) CP_ASYNC16(sb + aDst[i], aSrc[i] + adv);
#pragma unroll
        for (int i = 0; i < 4; i++) CP_ASYNC16(sb + bDst[i], bSrc[i] + adv);
        CP_COMMIT();
    }

    // 4x4 warp grid: warp tile 32 (m) x 64 (n)
    int wm = (warp & 3) * 32;
    int wn = (warp >> 2) * 64;
    int g  = lane >> 2;
    int tg = lane & 3;

    // A ldmatrix lane mapping (R9/R11-validated)
    uint32_t a_lrow = (uint32_t)((lane & 7) + ((lane >> 3) & 1) * 8);
    uint32_t a_boff = (uint32_t)((lane >> 4) * 16);
    // B ldmatrix lane mapping (R11-validated)
    uint32_t b_lrow = (uint32_t)(((lane >> 4) & 1) * 8 + (lane & 7));
    uint32_t b_boff = (uint32_t)(((lane >> 3) & 1) * 16);

    float acc[2][8][4];
#pragma unroll
    for (int i = 0; i < 2; i++)
#pragma unroll
        for (int j = 0; j < 8; j++)
#pragma unroll
            for (int r = 0; r < 4; r++) acc[i][j][r] = 0.f;

    for (int kt = 0; kt < NK; kt++) {
        CP_WAIT1();          // stage kt landed
        __syncthreads();     // all reads of stage (kt+2)%3 from iter kt-1 done

        uint32_t sbase = base0 + (kt % NSTAGE) * STAGE_BYTES;
        uint32_t aAddr[2];
#pragma unroll
        for (int i = 0; i < 2; i++)
            aAddr[i] = sbase + (wm + i * 16 + a_lrow) * (S_STRIDE * 4) + a_boff;
        uint32_t bAddr = sbase + A_STAGE_BYTES +
                         (wn + b_lrow) * (S_STRIDE * 4) + b_boff;

        int kn = kt + 2;
        uint32_t sbn = base0 + (kn % NSTAGE) * STAGE_BYTES;
        size_t adv = (size_t)kn * (BK * 4);

#pragma unroll
        for (int ks = 0; ks < 4; ks++) {
            uint32_t af[2][4];
#pragma unroll
            for (int i = 0; i < 2; i++)
                LDSM_X4(af[i][0], af[i][1], af[i][2], af[i][3], aAddr[i] + ks * 32);
            uint32_t bf[8][2];
#pragma unroll
            for (int jj = 0; jj < 4; jj++)
                LDSM_X4(bf[jj * 2][0], bf[jj * 2][1], bf[jj * 2 + 1][0], bf[jj * 2 + 1][1],
                        bAddr + jj * (16 * S_STRIDE * 4) + ks * 32);

            // hide next-stage cp.async issue in the mma shadow of ks==0
            if (ks == 0) {
                if (kn < NK) {
#pragma unroll
                    for (int i = 0; i < 2; i++) CP_ASYNC16(sbn + aDst[i], aSrc[i] + adv);
#pragma unroll
                    for (int i = 0; i < 4; i++) CP_ASYNC16(sbn + bDst[i], bSrc[i] + adv);
                }
                CP_COMMIT();
            }

#pragma unroll
            for (int i = 0; i < 2; i++)
#pragma unroll
                for (int j = 0; j < 8; j++) {
                    asm volatile(
                        "mma.sync.aligned.m16n8k8.row.col.f32.tf32.tf32.f32 "
                        "{%0,%1,%2,%3}, {%4,%5,%6,%7}, {%8,%9}, {%0,%1,%2,%3};\n"
                        : "+f"(acc[i][j][0]), "+f"(acc[i][j][1]),
                          "+f"(acc[i][j][2]), "+f"(acc[i][j][3])
                        : "r"(af[i][0]), "r"(af[i][1]), "r"(af[i][2]), "r"(af[i][3]),
                          "r"(bf[j][0]), "r"(bf[j][1]));
                }
        }
    }

    // epilogue
    const float* bias = biasB + (size_t)e * ND + n0;
    float* Cbase = (PHASE == 1) ? g_h : g_y;
#pragma unroll
    for (int i = 0; i < 2; i++) {
#pragma unroll
        for (int half = 0; half < 2; half++) {
            int ml = wm + i * 16 + g + half * 8;
            if (m0 + ml < cnt) {
                float* crow = Cbase + (size_t)(rbase + ml) * ND + n0;
#pragma unroll
                for (int j = 0; j < 8; j++) {
                    int nc = wn + j * 8 + tg * 2;
                    float c0 = acc[i][j][half * 2 + 0] + bias[nc];
                    float c1 = acc[i][j][half * 2 + 1] + bias[nc + 1];
                    if (PHASE == 1) {
                        c0 = rna_tf32(fmaxf(c0, 0.f));
                        c1 = rna_tf32(fmaxf(c1, 0.f));
                    }
                    float2 v; v.x = c0; v.y = c1;
                    *(float2*)(crow + nc) = v;
                }
            }
        }
    }
}

// ---------------- gated combine ----------------
__global__ void combine_kernel(float* __restrict__ out) {
    int idx = blockIdx.x * blockDim.x + threadIdx.x;
    int t = idx >> 8;
    int c = (idx & 255) * 4;
    int r0 = g_token_rows[2 * t];
    int r1 = g_token_rows[2 * t + 1];
    float w0 = g_gate[2 * t];
    float w1 = g_gate[2 * t + 1];
    float4 a = *(const float4*)(g_y + (size_t)r0 * ODIM + c);
    float4 b = *(const float4*)(g_y + (size_t)r1 * ODIM + c);
    float4 o;
    o.x = w0 * a.x + w1 * b.x;
    o.y = w0 * a.y + w1 * b.y;
    o.z = w0 * a.z + w1 * b.z;
    o.w = w0 * a.w + w1 * b.w;
    *(float4*)(out + (size_t)t * ODIM + c) = o;
}

// ---------------- launch ----------------
extern "C" void kernel_launch(void* const* d_in, const int* in_sizes, int n_in,
                              void* d_out, int out_size) {
    const float* x  = (const float*)d_in[0];
    const float* Wr = (const float*)d_in[1];
    const float* br = (const float*)d_in[2];
    const float* W1 = (const float*)d_in[3];
    const float* b1 = (const float*)d_in[4];
    const float* W2 = (const float*)d_in[5];
    const float* b2 = (const float*)d_in[6];
    float* out = (float*)d_out;

    cudaFuncSetAttribute(moe_gemm_kernel<1, DDIM, HDIM>,
                         cudaFuncAttributeMaxDynamicSharedMemorySize, DYN_SMEM);
    cudaFuncSetAttribute(moe_gemm_kernel<2, HDIM, ODIM>,
                         cudaFuncAttributeMaxDynamicSharedMemorySize, DYN_SMEM);

    // launch 1: round x + zero counts + transpose/round W1, W2
    prep_kernel<<<NB_RX + NT1 + NT2, 256>>>(x, W1, W2);
    // launch 2: router
    router_kernel<<<TNUM / 8, 256>>>(x, Wr, br);
    // launch 3: offsets (local) + row permutation
    build_rows_kernel<<<TNUM / 256, 256>>>();

    // launch 4: GEMM1 (ncu capture slot)
    dim3 g1(HDIM / BN, TNUM / BM, ENUM);   // (16, 32, 8)
    moe_gemm_kernel<1, DDIM, HDIM><<<g1, 512, DYN_SMEM>>>(b1);

    // launch 5: GEMM2
    dim3 g2(ODIM / BN, TNUM / BM, ENUM);   // (4, 32, 8)
    moe_gemm_kernel<2, HDIM, ODIM><<<g2, 512, DYN_SMEM>>>(b2);

    // launch 6: combine
    combine_kernel<<<TNUM, 256>>>(out);
}

// round 17
// speedup vs baseline: 1.2369x; 1.2369x over previous
#include <cuda_runtime.h>
#include <cstdint>
#include <math.h>

// Problem dims (fixed by setup_inputs)
#define TNUM 4096
#define DDIM 1024
#define HDIM 4096
#define ODIM 1024
#define ENUM 8
#define NROWS (TNUM * 2)

// ---------------- scratch (static __device__, no allocs) ----------------
// ONLY referenced from device code (host-side use passes shadow symbol!)
__device__ int   g_counts[ENUM];
__device__ int   g_offsets[ENUM];
__device__ int   g_e[NROWS];
__device__ int   g_pos[NROWS];
__device__ float g_gate[NROWS];
__device__ int   g_row_token[NROWS];
__device__ int   g_token_rows[NROWS];
__device__ float g_xr[(size_t)TNUM * DDIM];            // x rounded to tf32 (16 MB)
__device__ float g_w1t[(size_t)ENUM * HDIM * DDIM];    // W1^T rounded [E][H][D]
__device__ float g_w2t[(size_t)ENUM * ODIM * HDIM];    // W2^T rounded [E][O][H]
__device__ float g_h[(size_t)NROWS * HDIM];            // tf32-rounded intermediate
__device__ float g_y[(size_t)NROWS * ODIM];            // expert outputs

__device__ __forceinline__ float rna_tf32(float f) {
    uint32_t u;
    asm("cvt.rna.tf32.f32 %0, %1;" : "=r"(u) : "f"(f));
    return __uint_as_float(u);
}
__device__ __forceinline__ uint32_t smem_u32(const void* p) {
    uint32_t a;
    asm("{ .reg .u64 t; cvta.to.shared.u64 t, %1; cvt.u32.u64 %0, t; }" : "=r"(a) : "l"(p));
    return a;
}

// ---------------- mbarrier helpers ----------------
#define MBARRIER_INIT(addr, cnt) \
    asm volatile("mbarrier.init.shared.b64 [%0], %1;" :: "r"((uint32_t)(addr)), "r"((uint32_t)(cnt)) : "memory")
#define MBARRIER_ARRIVE(addr) \
    asm volatile("mbarrier.arrive.shared.b64 _, [%0];" :: "r"((uint32_t)(addr)) : "memory")
#define MBARRIER_WAIT_PARITY(addr, parity) do { \
    uint32_t _mbar = (uint32_t)(addr); uint32_t _par = (uint32_t)(parity); uint32_t _done; \
    asm volatile("{\n\t.reg .pred p;\n\t" \
        "mbarrier.try_wait.parity.acquire.cta.shared::cta.b64 p, [%1], %2;\n\t" \
        "selp.b32 %0, 1, 0, p;\n\t}" : "=r"(_done) : "r"(_mbar), "r"(_par) : "memory"); \
    if (!_done) { \
        asm volatile("{\n\t.reg .pred P1;\n\t" \
            "WL_%=:\n\t" \
            "mbarrier.try_wait.parity.acquire.cta.shared::cta.b64 P1, [%0], %1, 0x989680;\n\t" \
            "@P1 bra.uni WD_%=;\n\t" \
            "bra.uni WL_%=;\n\t" \
            "WD_%=:\n\t}" :: "r"(_mbar), "r"(_par) : "memory"); \
    } } while (0)

// ---------------- prep: round x + transpose/round W1, W2 (one launch) -------
#define NB_RX (TNUM * DDIM / 4 / 256)                       // 4096
#define NT1   ((HDIM / 32) * (DDIM / 32) * ENUM)            // 32768
#define NT2   ((ODIM / 32) * (HDIM / 32) * ENUM)            // 32768

__device__ __forceinline__ void transpose_round_tile(
    const float* __restrict__ W, float* __restrict__ Wt,
    int R, int C, int bb, int tid, float (*tile)[33]) {
    int nC = C / 32;
    int per = nC * (R / 32);
    int e = bb / per;
    int rem = bb % per;
    int c0 = (rem % nC) * 32;
    int r0 = (rem / nC) * 32;
    const float* Wp = W + (size_t)e * R * C;
    float* Op = Wt + (size_t)e * R * C;
    int tx = tid & 31, ty = tid >> 5;
#pragma unroll
    for (int i = 0; i < 4; i++)
        tile[ty + i * 8][tx] = Wp[(size_t)(r0 + ty + i * 8) * C + c0 + tx];
    __syncthreads();
#pragma unroll
    for (int i = 0; i < 4; i++)
        Op[(size_t)(c0 + ty + i * 8) * R + r0 + tx] = rna_tf32(tile[tx][ty + i * 8]);
}

__global__ void prep_kernel(const float* __restrict__ x,
                            const float* __restrict__ W1,
                            const float* __restrict__ W2) {
    __shared__ float tile[32][33];
    int b = blockIdx.x, tid = threadIdx.x;
    if (b < NB_RX) {
        if (b == 0 && tid < ENUM) g_counts[tid] = 0;
        int i = b * 256 + tid;
        float4 v = *(const float4*)(x + (size_t)i * 4);
        v.x = rna_tf32(v.x); v.y = rna_tf32(v.y);
        v.z = rna_tf32(v.z); v.w = rna_tf32(v.w);
        *(float4*)(g_xr + (size_t)i * 4) = v;
    } else if (b < NB_RX + NT1) {
        transpose_round_tile(W1, g_w1t, DDIM, HDIM, b - NB_RX, tid, tile);
    } else {
        transpose_round_tile(W2, g_w2t, HDIM, ODIM, b - NB_RX - NT1, tid, tile);
    }
}

// ---------------- router ----------------
__global__ void router_kernel(const float* __restrict__ x,
                              const float* __restrict__ Wr,
                              const float* __restrict__ br) {
    int warp = threadIdx.x >> 5;
    int lane = threadIdx.x & 31;
    int t = blockIdx.x * 8 + warp;
    if (t >= TNUM) return;
    const float* xr = x + (size_t)t * DDIM;
    float acc[ENUM];
#pragma unroll
    for (int e = 0; e < ENUM; e++) acc[e] = 0.f;
    for (int d = lane; d < DDIM; d += 32) {
        float xv = xr[d];
        const float* w = Wr + (size_t)d * ENUM;
#pragma unroll
        for (int e = 0; e < ENUM; e++) acc[e] = fmaf(xv, w[e], acc[e]);
    }
#pragma unroll
    for (int e = 0; e < ENUM; e++) {
#pragma unroll
        for (int s = 16; s > 0; s >>= 1)
            acc[e] += __shfl_xor_sync(0xffffffffu, acc[e], s);
    }
    if (lane == 0) {
        float v[ENUM];
#pragma unroll
        for (int e = 0; e < ENUM; e++) v[e] = acc[e] + br[e];
        int i0 = 0; float v0 = v[0];
#pragma unroll
        for (int e = 1; e < ENUM; e++) if (v[e] > v0) { v0 = v[e]; i0 = e; }
        int i1 = -1; float v1 = -1e30f;
#pragma unroll
        for (int e = 0; e < ENUM; e++)
            if (e != i0 && v[e] > v1) { v1 = v[e]; i1 = e; }
        float g0 = 1.f / (1.f + expf(v1 - v0));
        float g1 = 1.f - g0;
        int p0 = atomicAdd(&g_counts[i0], 1);
        int p1 = atomicAdd(&g_counts[i1], 1);
        g_e[2 * t]     = i0; g_pos[2 * t]     = p0; g_gate[2 * t]     = g0;
        g_e[2 * t + 1] = i1; g_pos[2 * t + 1] = p1; g_gate[2 * t + 1] = g1;
    }
}

// build_rows with per-block local offsets
__global__ void build_rows_kernel() {
    int off[ENUM];
    {
        int s = 0;
#pragma unroll
        for (int e = 0; e < ENUM; e++) { off[e] = s; s += g_counts[e]; }
    }
    if (blockIdx.x == 0 && threadIdx.x < ENUM) g_offsets[threadIdx.x] = off[threadIdx.x];
    int t = blockIdx.x * blockDim.x + threadIdx.x;
    if (t >= TNUM) return;
#pragma unroll
    for (int k = 0; k < 2; k++) {
        int e = g_e[2 * t + k];
        int row = off[e] + g_pos[2 * t + k];
        g_row_token[row] = t;
        g_token_rows[2 * t + k] = row;
    }
}

// -- grouped GEMM: 128x128, warp-specialized (8 consumers + 2 producers) -----
#define BM 128
#define BN 128
#define BK 32
#define S_STRIDE 36                                    // 144B rows, LDSM-safe
#define A_STAGE_BYTES (BM * S_STRIDE * 4)              // 18432
#define B_STAGE_BYTES (BN * S_STRIDE * 4)              // 18432
#define STAGE_BYTES (A_STAGE_BYTES + B_STAGE_BYTES)    // 36864
#define NSTAGE 3
#define DYN_SMEM (NSTAGE * STAGE_BYTES)                // 110592
#define NTHREADS 320                                   // 10 warps: 8 mma + 2 copy

#define CP_ASYNC16(dst, src) \
    asm volatile("cp.async.cg.shared.global [%0], [%1], 16;" \
                 :: "r"(dst), "l"(src) : "memory")
#define CP_COMMIT() asm volatile("cp.async.commit_group;" ::: "memory")
#define CP_WAIT1()  asm volatile("cp.async.wait_group 1;" ::: "memory")
#define CP_WAIT0()  asm volatile("cp.async.wait_group 0;" ::: "memory")

#define LDSM_X4(r0, r1, r2, r3, addr) \
    asm volatile("ldmatrix.sync.aligned.m8n8.x4.shared.b16 {%0,%1,%2,%3}, [%4];" \
                 : "=r"(r0), "=r"(r1), "=r"(r2), "=r"(r3) : "r"(addr))

// PHASE 1: A = g_xr gathered via row->token (K=DDIM), B = g_w1t, C = g_h
// PHASE 2: A = g_h direct rows (K=HDIM),             B = g_w2t, C = g_y
template <int PHASE, int KD, int ND>
__global__ void __launch_bounds__(NTHREADS, 2) moe_gemm_kernel(
    const float* __restrict__ biasB) {  // [E, ND] (harness ptr)
    int e = blockIdx.z;
    int cnt = g_counts[e];
    int m0 = blockIdx.y * BM;
    if (m0 >= cnt) return;
    int rbase = g_offsets[e] + m0;
    int n0 = blockIdx.x * BN;

    const float* Aglob = (PHASE == 1) ? g_xr  : g_h;    // device-side select
    const float* Btr   = (PHASE == 1) ? g_w1t : g_w2t;  // K-major rounded

    extern __shared__ __align__(16) char dynsmem[];
    __shared__ uint32_t sAoff[BM];
    __shared__ __align__(8) uint64_t s_mbar[NSTAGE * 2];

    uint32_t base0 = smem_u32(dynsmem);
    uint32_t mb = smem_u32(s_mbar);       // full[s]=mb+8s ; empty[s]=mb+24+8s

    int tid  = threadIdx.x;
    int lane = tid & 31;
    int warp = tid >> 5;                  // 0..9

    if (tid < BM) {
        uint32_t off = 0;
        if (m0 + tid < cnt) {
            int row = rbase + tid;
            off = (PHASE == 1) ? (uint32_t)g_row_token[row] * (uint32_t)KD
                               : (uint32_t)row * (uint32_t)KD;
        }
        sAoff[tid] = off;
    }
    if (tid == 0) {
#pragma unroll
        for (int s = 0; s < NSTAGE; s++) {
            MBARRIER_INIT(mb + s * 8, 2);        // full: 2 producer warps
            MBARRIER_INIT(mb + 24 + s * 8, 8);   // empty: 8 consumer warps
        }
    }
    __syncthreads();

    const int NK = KD / BK;

    if (warp >= 8) {
        // ================= PRODUCER (warps 8,9; 64 threads) =================
        int ptid = tid - 256;                 // 0..63
        int prow = ptid >> 3;                 // base row 0..7 (+8 per i)
        int pgg  = ptid & 7;                  // 16B granule in 128B k-row
        uint32_t aOff[16];
#pragma unroll
        for (int i = 0; i < 16; i++)
            aOff[i] = sAoff[prow + 8 * i] * 4u + (uint32_t)pgg * 16u;
        size_t bOff0 = ((size_t)(e * ND + n0) + prow) * (size_t)KD * 4 + pgg * 16;
        const size_t bStep = (size_t)8 * KD * 4;
        uint32_t dA0 = (uint32_t)(prow * (S_STRIDE * 4) + pgg * 16);
        uint32_t dB0 = A_STAGE_BYTES + dA0;

        for (int k = 0; k < NK; k++) {
            if (k >= NSTAGE)
                MBARRIER_WAIT_PARITY(mb + 24 + (k % NSTAGE) * 8,
                                     (uint32_t)(((k / NSTAGE) - 1) & 1));
            uint32_t sb = base0 + (k % NSTAGE) * STAGE_BYTES;
            uint32_t adv = (uint32_t)k * (BK * 4);
#pragma unroll
            for (int i = 0; i < 16; i++) {
                CP_ASYNC16(sb + dA0 + i * (8 * S_STRIDE * 4),
                           (const char*)Aglob + aOff[i] + adv);
                CP_ASYNC16(sb + dB0 + i * (8 * S_STRIDE * 4),
                           (const char*)Btr + bOff0 + (size_t)i * bStep + adv);
            }
            CP_COMMIT();
            if (k >= 1) {
                CP_WAIT1();                    // group k-1 (and older) done
                if (lane == 0) MBARRIER_ARRIVE(mb + ((k - 1) % NSTAGE) * 8);
            }
        }
        CP_WAIT0();
        if (lane == 0) MBARRIER_ARRIVE(mb + ((NK - 1) % NSTAGE) * 8);
        return;   // producers exit; no further CTA-wide syncs exist
    }

    // ================= CONSUMER (warps 0..7) =================
    int wm = (warp >> 2) * 64;
    int wn = (warp & 3) * 32;
    int g  = lane >> 2;
    int tg = lane & 3;

    uint32_t a_lrow = (uint32_t)((lane & 7) + ((lane >> 3) & 1) * 8);
    uint32_t a_boff = (uint32_t)((lane >> 4) * 16);
    uint32_t b_lrow = (uint32_t)(((lane >> 4) & 1) * 8 + (lane & 7));
    uint32_t b_boff = (uint32_t)(((lane >> 3) & 1) * 16);

    float acc[4][4][4];
#pragma unroll
    for (int i = 0; i < 4; i++)
#pragma unroll
        for (int j = 0; j < 4; j++)
#pragma unroll
            for (int r = 0; r < 4; r++) acc[i][j][r] = 0.f;

    for (int kt = 0; kt < NK; kt++) {
        int s = kt % NSTAGE;
        MBARRIER_WAIT_PARITY(mb + s * 8, (uint32_t)((kt / NSTAGE) & 1));

        uint32_t sbase = base0 + s * STAGE_BYTES;
        uint32_t aAddr[4];
#pragma unroll
        for (int i = 0; i < 4; i++)
            aAddr[i] = sbase + (wm + i * 16 + a_lrow) * (S_STRIDE * 4) + a_boff;
        uint32_t bAddr = sbase + A_STAGE_BYTES +
                         (wn + b_lrow) * (S_STRIDE * 4) + b_boff;

#pragma unroll
        for (int ks = 0; ks < 4; ks++) {
            uint32_t af[4][4];
#pragma unroll
            for (int i = 0; i < 4; i++)
                LDSM_X4(af[i][0], af[i][1], af[i][2], af[i][3], aAddr[i] + ks * 32);
            uint32_t bf[4][2];
            LDSM_X4(bf[0][0], bf[0][1], bf[1][0], bf[1][1], bAddr + ks * 32);
            LDSM_X4(bf[2][0], bf[2][1], bf[3][0], bf[3][1],
                    bAddr + 16 * (S_STRIDE * 4) + ks * 32);
#pragma unroll
            for (int i = 0; i < 4; i++)
#pragma unroll
                for (int j = 0; j < 4; j++) {
                    asm volatile(
                        "mma.sync.aligned.m16n8k8.row.col.f32.tf32.tf32.f32 "
                        "{%0,%1,%2,%3}, {%4,%5,%6,%7}, {%8,%9}, {%0,%1,%2,%3};\n"
                        : "+f"(acc[i][j][0]), "+f"(acc[i][j][1]),
                          "+f"(acc[i][j][2]), "+f"(acc[i][j][3])
                        : "r"(af[i][0]), "r"(af[i][1]), "r"(af[i][2]), "r"(af[i][3]),
                          "r"(bf[j][0]), "r"(bf[j][1]));
                }
        }
        // all frag data consumed by the converged mma.sync above -> release buffer
        if (lane == 0) MBARRIER_ARRIVE(mb + 24 + s * 8);
    }

    // epilogue (consumer warps only)
    const float* bias = biasB + (size_t)e * ND + n0;
    float* Cbase = (PHASE == 1) ? g_h : g_y;
#pragma unroll
    for (int i = 0; i < 4; i++) {
#pragma unroll
        for (int half = 0; half < 2; half++) {
            int ml = wm + i * 16 + g + half * 8;
            if (m0 + ml < cnt) {
                float* crow = Cbase + (size_t)(rbase + ml) * ND + n0;
#pragma unroll
                for (int j = 0; j < 4; j++) {
                    int nc = wn + j * 8 + tg * 2;
                    float c0 = acc[i][j][half * 2 + 0] + bias[nc];
                    float c1 = acc[i][j][half * 2 + 1] + bias[nc + 1];
                    if (PHASE == 1) {
                        c0 = rna_tf32(fmaxf(c0, 0.f));
                        c1 = rna_tf32(fmaxf(c1, 0.f));
                    }
                    float2 v; v.x = c0; v.y = c1;
                    *(float2*)(crow + nc) = v;
                }
            }
        }
    }
}

// ---------------- gated combine ----------------
__global__ void combine_kernel(float* __restrict__ out) {
    int idx = blockIdx.x * blockDim.x + threadIdx.x;
    int t = idx >> 8;
    int c = (idx & 255) * 4;
    int r0 = g_token_rows[2 * t];
    int r1 = g_token_rows[2 * t + 1];
    float w0 = g_gate[2 * t];
    float w1 = g_gate[2 * t + 1];
    float4 a = *(const float4*)(g_y + (size_t)r0 * ODIM + c);
    float4 b = *(const float4*)(g_y + (size_t)r1 * ODIM + c);
    float4 o;
    o.x = w0 * a.x + w1 * b.x;
    o.y = w0 * a.y + w1 * b.y;
    o.z = w0 * a.z + w1 * b.z;
    o.w = w0 * a.w + w1 * b.w;
    *(float4*)(out + (size_t)t * ODIM + c) = o;
}

// ---------------- launch ----------------
extern "C" void kernel_launch(void* const* d_in, const int* in_sizes, int n_in,
                              void* d_out, int out_size) {
    const float* x  = (const float*)d_in[0];
    const float* Wr = (const float*)d_in[1];
    const float* br = (const float*)d_in[2];
    const float* W1 = (const float*)d_in[3];
    const float* b1 = (const float*)d_in[4];
    const float* W2 = (const float*)d_in[5];
    const float* b2 = (const float*)d_in[6];
    float* out = (float*)d_out;

    cudaFuncSetAttribute(moe_gemm_kernel<1, DDIM, HDIM>,
                         cudaFuncAttributeMaxDynamicSharedMemorySize, DYN_SMEM);
    cudaFuncSetAttribute(moe_gemm_kernel<2, HDIM, ODIM>,
                         cudaFuncAttributeMaxDynamicSharedMemorySize, DYN_SMEM);

    // launch 1: round x + zero counts + transpose/round W1, W2
    prep_kernel<<<NB_RX + NT1 + NT2, 256>>>(x, W1, W2);
    // launch 2: router
    router_kernel<<<TNUM / 8, 256>>>(x, Wr, br);
    // launch 3: offsets (local) + row permutation
    build_rows_kernel<<<TNUM / 256, 256>>>();

    // launch 4: GEMM1 (ncu capture slot)
    dim3 g1(HDIM / BN, TNUM / BM, ENUM);   // (32, 32, 8)
    moe_gemm_kernel<1, DDIM, HDIM><<<g1, NTHREADS, DYN_SMEM>>>(b1);

    // launch 5: GEMM2
    dim3 g2(ODIM / BN, TNUM / BM, ENUM);   // (8, 32, 8)
    moe_gemm_kernel<2, HDIM, ODIM><<<g2, NTHREADS, DYN_SMEM>>>(b2);

    // launch 6: combine
    combine_kernel<<<TNUM, 256>>>(out);
}